// round 1
// baseline (speedup 1.0000x reference)
#include <cuda_runtime.h>
#include <cuda_bf16.h>
#include <math.h>

// Problem constants
#define BATCH 4
#define SEQ   2048
#define EMB   1024
#define MROWS (BATCH * SEQ)        // 8192

// Scratch (allocation-free rule: __device__ globals)
__device__ float g_K[BATCH * SEQ * EMB];   // 32 MB
__device__ float g_Q[BATCH * SEQ * EMB];   // 32 MB
__device__ float g_V[BATCH * SEQ * EMB];   // 32 MB
__device__ float g_S[BATCH * SEQ * SEQ];   // 64 MB (sim / attn probs)

// ----------------------------------------------------------------------------
// NT SGEMM: C[m,n] = scale * sum_k A[m,k] * B[n,k]  (+ bias[n])
// A: [M x K] row-major, B: [N x K] row-major. 128x128x8 blocking, 256 thr.
// CAUSAL_SKIP: skip blocks entirely above the diagonal (n0 > m0+127).
// ----------------------------------------------------------------------------
template<bool ADD_BIAS, bool CAUSAL_SKIP>
__global__ __launch_bounds__(256)
void gemm_nt_kernel(const float* __restrict__ A,
                    const float* __restrict__ B,
                    const float* __restrict__ bias,
                    float* __restrict__ C,
                    int M, int N, int K, float scale,
                    size_t strideA, size_t strideB, size_t strideC)
{
    const int m0 = blockIdx.y * 128;
    const int n0 = blockIdx.x * 128;
    if (CAUSAL_SKIP && n0 > m0 + 127) return;

    const int b = blockIdx.z;
    A += (size_t)b * strideA;
    B += (size_t)b * strideB;
    C += (size_t)b * strideC;

    __shared__ float As[8][128];
    __shared__ float Bs[8][128];

    const int tid  = threadIdx.x;
    const int la_m = tid >> 1;          // 0..127 (row within tile)
    const int la_k = (tid & 1) * 4;     // 0 or 4

    const int ty = tid >> 4;            // 0..15
    const int tx = tid & 15;            // 0..15

    float acc[8][8];
    #pragma unroll
    for (int i = 0; i < 8; i++)
        #pragma unroll
        for (int j = 0; j < 8; j++) acc[i][j] = 0.f;

    const float* Ab = A + (size_t)m0 * K;
    const float* Bb = B + (size_t)n0 * K;

    for (int k0 = 0; k0 < K; k0 += 8) {
        float4 av = *(const float4*)(Ab + (size_t)la_m * K + k0 + la_k);
        float4 bv = *(const float4*)(Bb + (size_t)la_m * K + k0 + la_k);
        As[la_k + 0][la_m] = av.x;
        As[la_k + 1][la_m] = av.y;
        As[la_k + 2][la_m] = av.z;
        As[la_k + 3][la_m] = av.w;
        Bs[la_k + 0][la_m] = bv.x;
        Bs[la_k + 1][la_m] = bv.y;
        Bs[la_k + 2][la_m] = bv.z;
        Bs[la_k + 3][la_m] = bv.w;
        __syncthreads();

        #pragma unroll
        for (int kk = 0; kk < 8; kk++) {
            float a[8], bb[8];
            float4 a0 = *(const float4*)&As[kk][ty * 8];
            float4 a1 = *(const float4*)&As[kk][ty * 8 + 4];
            float4 b0 = *(const float4*)&Bs[kk][tx * 8];
            float4 b1 = *(const float4*)&Bs[kk][tx * 8 + 4];
            a[0]=a0.x; a[1]=a0.y; a[2]=a0.z; a[3]=a0.w;
            a[4]=a1.x; a[5]=a1.y; a[6]=a1.z; a[7]=a1.w;
            bb[0]=b0.x; bb[1]=b0.y; bb[2]=b0.z; bb[3]=b0.w;
            bb[4]=b1.x; bb[5]=b1.y; bb[6]=b1.z; bb[7]=b1.w;
            #pragma unroll
            for (int i = 0; i < 8; i++)
                #pragma unroll
                for (int j = 0; j < 8; j++)
                    acc[i][j] = fmaf(a[i], bb[j], acc[i][j]);
        }
        __syncthreads();
    }

    #pragma unroll
    for (int i = 0; i < 8; i++) {
        const int m = m0 + ty * 8 + i;
        float* Crow = C + (size_t)m * N + n0 + tx * 8;
        #pragma unroll
        for (int j = 0; j < 8; j++) {
            float v = acc[i][j] * scale;
            if (ADD_BIAS) v += bias[n0 + tx * 8 + j];
            Crow[j] = v;
        }
    }
}

// ----------------------------------------------------------------------------
// NN SGEMM: C[m,n] = sum_k A[m,k] * B[k,n]
// A: [M x K] row-major (P), B: [K x N] row-major (V).
// CAUSAL_KLIMIT: only accumulate k < m0+128 (P is zero above diagonal).
// ----------------------------------------------------------------------------
__global__ __launch_bounds__(256)
void gemm_nn_causal_kernel(const float* __restrict__ A,
                           const float* __restrict__ B,
                           float* __restrict__ C,
                           int M, int N, int K,
                           size_t strideA, size_t strideB, size_t strideC)
{
    const int m0 = blockIdx.y * 128;
    const int n0 = blockIdx.x * 128;

    const int b = blockIdx.z;
    A += (size_t)b * strideA;
    B += (size_t)b * strideB;
    C += (size_t)b * strideC;

    __shared__ float As[8][128];
    __shared__ float Bs[8][128];

    const int tid  = threadIdx.x;
    // A load (transpose on load): row la_m, k offset la_k
    const int la_m = tid >> 1;
    const int la_k = (tid & 1) * 4;
    // B load (direct): row kr, col nc
    const int kr = tid >> 5;            // 0..7
    const int nc = (tid & 31) * 4;      // 0..124

    const int ty = tid >> 4;
    const int tx = tid & 15;

    float acc[8][8];
    #pragma unroll
    for (int i = 0; i < 8; i++)
        #pragma unroll
        for (int j = 0; j < 8; j++) acc[i][j] = 0.f;

    const float* Ab = A + (size_t)m0 * K;

    const int kmax = (m0 + 128 < K) ? (m0 + 128) : K;   // causal limit

    for (int k0 = 0; k0 < kmax; k0 += 8) {
        float4 av = *(const float4*)(Ab + (size_t)la_m * K + k0 + la_k);
        As[la_k + 0][la_m] = av.x;
        As[la_k + 1][la_m] = av.y;
        As[la_k + 2][la_m] = av.z;
        As[la_k + 3][la_m] = av.w;
        float4 bv = *(const float4*)(B + (size_t)(k0 + kr) * N + n0 + nc);
        *(float4*)&Bs[kr][nc] = bv;
        __syncthreads();

        #pragma unroll
        for (int kk = 0; kk < 8; kk++) {
            float a[8], bb[8];
            float4 a0 = *(const float4*)&As[kk][ty * 8];
            float4 a1 = *(const float4*)&As[kk][ty * 8 + 4];
            float4 b0 = *(const float4*)&Bs[kk][tx * 8];
            float4 b1 = *(const float4*)&Bs[kk][tx * 8 + 4];
            a[0]=a0.x; a[1]=a0.y; a[2]=a0.z; a[3]=a0.w;
            a[4]=a1.x; a[5]=a1.y; a[6]=a1.z; a[7]=a1.w;
            bb[0]=b0.x; bb[1]=b0.y; bb[2]=b0.z; bb[3]=b0.w;
            bb[4]=b1.x; bb[5]=b1.y; bb[6]=b1.z; bb[7]=b1.w;
            #pragma unroll
            for (int i = 0; i < 8; i++)
                #pragma unroll
                for (int j = 0; j < 8; j++)
                    acc[i][j] = fmaf(a[i], bb[j], acc[i][j]);
        }
        __syncthreads();
    }

    #pragma unroll
    for (int i = 0; i < 8; i++) {
        const int m = m0 + ty * 8 + i;
        float* Crow = C + (size_t)m * N + n0 + tx * 8;
        #pragma unroll
        for (int j = 0; j < 8; j++) Crow[j] = acc[i][j];
    }
}

// ----------------------------------------------------------------------------
// Causal softmax over last dim. One block per row. Writes 0 above diagonal.
// ----------------------------------------------------------------------------
__global__ __launch_bounds__(256)
void softmax_causal_kernel(float* __restrict__ S)
{
    const int row   = blockIdx.x;            // 0 .. BATCH*SEQ-1
    const int s     = row & (SEQ - 1);       // position within sequence
    float* p = S + (size_t)row * SEQ;

    const int tid = threadIdx.x;
    __shared__ float red[32];

    // max over t <= s
    float lmax = -INFINITY;
    for (int t = tid; t <= s; t += 256)
        lmax = fmaxf(lmax, p[t]);
    #pragma unroll
    for (int o = 16; o > 0; o >>= 1)
        lmax = fmaxf(lmax, __shfl_xor_sync(0xffffffffu, lmax, o));
    if ((tid & 31) == 0) red[tid >> 5] = lmax;
    __syncthreads();
    if (tid < 32) {
        float v = red[tid & 7];
        #pragma unroll
        for (int o = 4; o > 0; o >>= 1)
            v = fmaxf(v, __shfl_xor_sync(0xffffffffu, v, o));
        red[0] = v;
    }
    __syncthreads();
    const float rmax = red[0];
    __syncthreads();

    // sum of exp
    float lsum = 0.f;
    for (int t = tid; t <= s; t += 256)
        lsum += __expf(p[t] - rmax);
    #pragma unroll
    for (int o = 16; o > 0; o >>= 1)
        lsum += __shfl_xor_sync(0xffffffffu, lsum, o);
    if ((tid & 31) == 0) red[tid >> 5] = lsum;
    __syncthreads();
    if (tid < 32) {
        float v = red[tid & 7];
        #pragma unroll
        for (int o = 4; o > 0; o >>= 1)
            v += __shfl_xor_sync(0xffffffffu, v, o);
        red[0] = v;
    }
    __syncthreads();
    const float inv = 1.f / red[0];

    for (int t = tid; t < SEQ; t += 256)
        p[t] = (t <= s) ? __expf(p[t] - rmax) * inv : 0.f;
}

// ----------------------------------------------------------------------------
// Launch
// ----------------------------------------------------------------------------
extern "C" void kernel_launch(void* const* d_in, const int* in_sizes, int n_in,
                              void* d_out, int out_size)
{
    const float* x  = (const float*)d_in[0];
    const float* Wk = (const float*)d_in[1];
    const float* bk = (const float*)d_in[2];
    const float* Wq = (const float*)d_in[3];
    const float* bq = (const float*)d_in[4];
    const float* Wv = (const float*)d_in[5];
    const float* bv = (const float*)d_in[6];
    float* out = (float*)d_out;

    float* K; cudaGetSymbolAddress((void**)&K, g_K);
    float* Q; cudaGetSymbolAddress((void**)&Q, g_Q);
    float* V; cudaGetSymbolAddress((void**)&V, g_V);
    float* S; cudaGetSymbolAddress((void**)&S, g_S);

    // 1) Projections: [8192 x 1024] = x @ W^T + b   (NT, no batching)
    {
        dim3 grid(EMB / 128, MROWS / 128, 1);
        gemm_nt_kernel<true, false><<<grid, 256>>>(x, Wk, bk, K, MROWS, EMB, EMB, 1.f, 0, 0, 0);
        gemm_nt_kernel<true, false><<<grid, 256>>>(x, Wq, bq, Q, MROWS, EMB, EMB, 1.f, 0, 0, 0);
        gemm_nt_kernel<true, false><<<grid, 256>>>(x, Wv, bv, V, MROWS, EMB, EMB, 1.f, 0, 0, 0);
    }

    // 2) sim = K @ Q^T / sqrt(E), batched, causal block skip
    {
        dim3 grid(SEQ / 128, SEQ / 128, BATCH);
        const float scale = 1.f / sqrtf((float)EMB);
        gemm_nt_kernel<false, true><<<grid, 256>>>(
            K, Q, nullptr, S, SEQ, SEQ, EMB, scale,
            (size_t)SEQ * EMB, (size_t)SEQ * EMB, (size_t)SEQ * SEQ);
    }

    // 3) causal softmax rows
    softmax_causal_kernel<<<BATCH * SEQ, 256>>>(S);

    // 4) out = P @ V, batched, k-limited by causality
    {
        dim3 grid(EMB / 128, SEQ / 128, BATCH);
        gemm_nn_causal_kernel<<<grid, 256>>>(
            S, V, out, SEQ, EMB, SEQ,
            (size_t)SEQ * SEQ, (size_t)SEQ * EMB, (size_t)SEQ * EMB);
    }
}

// round 2
// speedup vs baseline: 3.5516x; 3.5516x over previous
#include <cuda_runtime.h>
#include <cuda_bf16.h>
#include <math.h>

// Problem constants
#define BATCH 4
#define SEQ   2048
#define EMB   1024
#define MROWS (BATCH * SEQ)        // 8192

#define BM 128
#define BN 128
#define BK 16
#define ASTRIDE 20          // [row][k] tiles: stride 20 -> banks (20g+c)%32 distinct
#define BSTRIDE_NN 136      // [k][n] tile: stride 136 -> banks (8c+g)%32 distinct

// Scratch (allocation-free rule: __device__ globals)
__device__ float g_K[BATCH * SEQ * EMB];   // 32 MB
__device__ float g_Q[BATCH * SEQ * EMB];   // 32 MB
__device__ float g_V[BATCH * SEQ * EMB];   // 32 MB
__device__ float g_S[BATCH * SEQ * SEQ];   // 64 MB (sim / attn probs)

// ---------------------------------------------------------------------------
// PTX helpers
// ---------------------------------------------------------------------------
__device__ __forceinline__ void cp16(void* smem, const void* gmem) {
    unsigned s = (unsigned)__cvta_generic_to_shared(smem);
    asm volatile("cp.async.cg.shared.global [%0], [%1], 16;" :: "r"(s), "l"(gmem));
}
__device__ __forceinline__ void cp_commit() {
    asm volatile("cp.async.commit_group;");
}
template<int N>
__device__ __forceinline__ void cp_wait() {
    asm volatile("cp.async.wait_group %0;" :: "n"(N));
}
__device__ __forceinline__ unsigned f2tf32(float x) {
    unsigned r;
    asm("cvt.rna.tf32.f32 %0, %1;" : "=r"(r) : "f"(x));
    return r;
}
__device__ __forceinline__ void mma_tf32(float* d, const unsigned* a, const unsigned* b) {
    asm volatile(
        "mma.sync.aligned.m16n8k8.row.col.f32.tf32.tf32.f32 "
        "{%0,%1,%2,%3}, {%4,%5,%6,%7}, {%8,%9}, {%0,%1,%2,%3};\n"
        : "+f"(d[0]), "+f"(d[1]), "+f"(d[2]), "+f"(d[3])
        : "r"(a[0]), "r"(a[1]), "r"(a[2]), "r"(a[3]),
          "r"(b[0]), "r"(b[1]));
}

// ---------------------------------------------------------------------------
// NT tf32 GEMM: C[m,n] = scale * sum_k A[m,k]*B[n,k] (+bias[n])
// A: [M x K] rm, B: [N x K] rm. 128x128x16 tiles, 8 warps (each 32x64).
// PROJ3: blockIdx.z in {0,1,2} selects (Wk,bk,K)/(Wq,bq,Q)/(Wv,bv,V).
// CAUSAL_SKIP: skip tiles fully above diagonal.
// ---------------------------------------------------------------------------
template<bool PROJ3, bool CAUSAL_SKIP>
__global__ __launch_bounds__(256)
void gemm_nt_tf32(const float* __restrict__ A,
                  const float* __restrict__ B0, const float* __restrict__ B1, const float* __restrict__ B2,
                  const float* __restrict__ bias0, const float* __restrict__ bias1, const float* __restrict__ bias2,
                  float* __restrict__ C0, float* __restrict__ C1, float* __restrict__ C2,
                  int M, int N, int K, float scale,
                  size_t sA, size_t sB, size_t sC)
{
    const int m0 = blockIdx.y * BM;
    const int n0 = blockIdx.x * BN;
    if (CAUSAL_SKIP && n0 > m0 + BM - 1) return;

    const int z = blockIdx.z;
    const float* A_ = A;
    const float* B_;
    const float* bias_;
    float* C_;
    if (PROJ3) {
        B_    = (z == 0) ? B0 : (z == 1) ? B1 : B2;
        bias_ = (z == 0) ? bias0 : (z == 1) ? bias1 : bias2;
        C_    = (z == 0) ? C0 : (z == 1) ? C1 : C2;
    } else {
        A_ = A + (size_t)z * sA;
        B_ = B0 + (size_t)z * sB;
        C_ = C0 + (size_t)z * sC;
        bias_ = nullptr;
    }

    __shared__ float As[2][BM][ASTRIDE];
    __shared__ float Bs[2][BN][ASTRIDE];

    const int tid  = threadIdx.x;
    const int warp = tid >> 5, lane = tid & 31;
    const int wm = warp >> 1, wn = warp & 1;
    const int g = lane >> 2, c = lane & 3;

    // global->smem indices: 64 rows per pass, 4 threads per row (16 floats)
    const int lrow = tid >> 2;
    const int lc4  = (tid & 3) * 4;

    const float* Ag = A_ + (size_t)(m0 + lrow) * K + lc4;
    const float* Bg = B_ + (size_t)(n0 + lrow) * K + lc4;

    float acc[2][8][4];
    #pragma unroll
    for (int i = 0; i < 2; i++)
        #pragma unroll
        for (int j = 0; j < 8; j++)
            #pragma unroll
            for (int r = 0; r < 4; r++) acc[i][j][r] = 0.f;

    const int NIT = K / BK;

    // prologue
    {
        cp16(&As[0][lrow][lc4],      Ag);
        cp16(&As[0][lrow + 64][lc4], Ag + (size_t)64 * K);
        cp16(&Bs[0][lrow][lc4],      Bg);
        cp16(&Bs[0][lrow + 64][lc4], Bg + (size_t)64 * K);
        cp_commit();
    }

    for (int it = 0; it < NIT; ++it) {
        const int nxt = it + 1;
        if (nxt < NIT) {
            const int k0 = nxt * BK;
            const int buf = nxt & 1;
            cp16(&As[buf][lrow][lc4],      Ag + k0);
            cp16(&As[buf][lrow + 64][lc4], Ag + (size_t)64 * K + k0);
            cp16(&Bs[buf][lrow][lc4],      Bg + k0);
            cp16(&Bs[buf][lrow + 64][lc4], Bg + (size_t)64 * K + k0);
        }
        cp_commit();
        cp_wait<1>();
        __syncthreads();

        const int buf = it & 1;
        #pragma unroll
        for (int kk = 0; kk < BK; kk += 8) {
            unsigned af[2][4];
            #pragma unroll
            for (int i = 0; i < 2; i++) {
                const int mb = wm * 32 + i * 16;
                af[i][0] = f2tf32(As[buf][mb + g][kk + c]);
                af[i][1] = f2tf32(As[buf][mb + 8 + g][kk + c]);
                af[i][2] = f2tf32(As[buf][mb + g][kk + c + 4]);
                af[i][3] = f2tf32(As[buf][mb + 8 + g][kk + c + 4]);
            }
            unsigned bf[8][2];
            #pragma unroll
            for (int j = 0; j < 8; j++) {
                const int nb = wn * 64 + j * 8;
                bf[j][0] = f2tf32(Bs[buf][nb + g][kk + c]);
                bf[j][1] = f2tf32(Bs[buf][nb + g][kk + c + 4]);
            }
            #pragma unroll
            for (int i = 0; i < 2; i++)
                #pragma unroll
                for (int j = 0; j < 8; j++)
                    mma_tf32(acc[i][j], af[i], bf[j]);
        }
        __syncthreads();
    }

    // epilogue
    #pragma unroll
    for (int i = 0; i < 2; i++) {
        const int r0 = m0 + wm * 32 + i * 16 + g;
        #pragma unroll
        for (int j = 0; j < 8; j++) {
            const int col = n0 + wn * 64 + j * 8 + 2 * c;
            float2 v0, v1;
            v0.x = acc[i][j][0] * scale; v0.y = acc[i][j][1] * scale;
            v1.x = acc[i][j][2] * scale; v1.y = acc[i][j][3] * scale;
            if (PROJ3) {
                v0.x += bias_[col]; v0.y += bias_[col + 1];
                v1.x += bias_[col]; v1.y += bias_[col + 1];
            }
            *(float2*)&C_[(size_t)r0 * N + col]       = v0;
            *(float2*)&C_[(size_t)(r0 + 8) * N + col] = v1;
        }
    }
}

// ---------------------------------------------------------------------------
// NN tf32 GEMM (P @ V): C[m,n] = sum_k A[m,k]*B[k,n], k limited to m0+128
// A: [M x K] rm (P, zero above diagonal), B: [K x N] rm.
// ---------------------------------------------------------------------------
__global__ __launch_bounds__(256)
void gemm_nn_tf32_causal(const float* __restrict__ A,
                         const float* __restrict__ B,
                         float* __restrict__ C,
                         int M, int N, int K,
                         size_t sA, size_t sB, size_t sC)
{
    const int m0 = blockIdx.y * BM;
    const int n0 = blockIdx.x * BN;
    const int z  = blockIdx.z;
    const float* A_ = A + (size_t)z * sA;
    const float* B_ = B + (size_t)z * sB;
    float*       C_ = C + (size_t)z * sC;

    __shared__ float As[2][BM][ASTRIDE];
    __shared__ float Bs[2][BK][BSTRIDE_NN];

    const int tid  = threadIdx.x;
    const int warp = tid >> 5, lane = tid & 31;
    const int wm = warp >> 1, wn = warp & 1;
    const int g = lane >> 2, c = lane & 3;

    // A loads: 64 rows/pass, 4 thr/row
    const int larow = tid >> 2;
    const int lac4  = (tid & 3) * 4;
    // B loads: 8 k-rows/pass, 32 thr/row
    const int lbk  = tid >> 5;
    const int lbn4 = (tid & 31) * 4;

    const float* Ag = A_ + (size_t)(m0 + larow) * K + lac4;
    const float* Bg = B_ + (size_t)lbk * N + n0 + lbn4;

    float acc[2][8][4];
    #pragma unroll
    for (int i = 0; i < 2; i++)
        #pragma unroll
        for (int j = 0; j < 8; j++)
            #pragma unroll
            for (int r = 0; r < 4; r++) acc[i][j][r] = 0.f;

    const int kmax = (m0 + BM < K) ? (m0 + BM) : K;   // causal limit
    const int NIT = kmax / BK;

    {
        cp16(&As[0][larow][lac4],      Ag);
        cp16(&As[0][larow + 64][lac4], Ag + (size_t)64 * K);
        cp16(&Bs[0][lbk][lbn4],        Bg);
        cp16(&Bs[0][lbk + 8][lbn4],    Bg + (size_t)8 * N);
        cp_commit();
    }

    for (int it = 0; it < NIT; ++it) {
        const int nxt = it + 1;
        if (nxt < NIT) {
            const int k0 = nxt * BK;
            const int buf = nxt & 1;
            cp16(&As[buf][larow][lac4],      Ag + k0);
            cp16(&As[buf][larow + 64][lac4], Ag + (size_t)64 * K + k0);
            cp16(&Bs[buf][lbk][lbn4],        Bg + (size_t)k0 * N);
            cp16(&Bs[buf][lbk + 8][lbn4],    Bg + (size_t)(k0 + 8) * N);
        }
        cp_commit();
        cp_wait<1>();
        __syncthreads();

        const int buf = it & 1;
        #pragma unroll
        for (int kk = 0; kk < BK; kk += 8) {
            unsigned af[2][4];
            #pragma unroll
            for (int i = 0; i < 2; i++) {
                const int mb = wm * 32 + i * 16;
                af[i][0] = f2tf32(As[buf][mb + g][kk + c]);
                af[i][1] = f2tf32(As[buf][mb + 8 + g][kk + c]);
                af[i][2] = f2tf32(As[buf][mb + g][kk + c + 4]);
                af[i][3] = f2tf32(As[buf][mb + 8 + g][kk + c + 4]);
            }
            unsigned bf[8][2];
            #pragma unroll
            for (int j = 0; j < 8; j++) {
                const int nb = wn * 64 + j * 8;
                bf[j][0] = f2tf32(Bs[buf][kk + c][nb + g]);
                bf[j][1] = f2tf32(Bs[buf][kk + c + 4][nb + g]);
            }
            #pragma unroll
            for (int i = 0; i < 2; i++)
                #pragma unroll
                for (int j = 0; j < 8; j++)
                    mma_tf32(acc[i][j], af[i], bf[j]);
        }
        __syncthreads();
    }

    #pragma unroll
    for (int i = 0; i < 2; i++) {
        const int r0 = m0 + wm * 32 + i * 16 + g;
        #pragma unroll
        for (int j = 0; j < 8; j++) {
            const int col = n0 + wn * 64 + j * 8 + 2 * c;
            float2 v0, v1;
            v0.x = acc[i][j][0]; v0.y = acc[i][j][1];
            v1.x = acc[i][j][2]; v1.y = acc[i][j][3];
            *(float2*)&C_[(size_t)r0 * N + col]       = v0;
            *(float2*)&C_[(size_t)(r0 + 8) * N + col] = v1;
        }
    }
}

// ---------------------------------------------------------------------------
// Causal softmax over last dim. One block per row; row cached in smem;
// one gmem read + one gmem write. Writes exact 0 above diagonal.
// ---------------------------------------------------------------------------
__global__ __launch_bounds__(256)
void softmax_causal_kernel(float* __restrict__ S)
{
    const int row = blockIdx.x;
    const int s   = row & (SEQ - 1);
    float* p = S + (size_t)row * SEQ;

    __shared__ float buf[SEQ];
    __shared__ float red[8];

    const int tid = threadIdx.x;

    // pass 1: load + max
    float lmax = -INFINITY;
    for (int t = tid; t <= s; t += 256) {
        const float v = p[t];
        buf[t] = v;
        lmax = fmaxf(lmax, v);
    }
    #pragma unroll
    for (int o = 16; o > 0; o >>= 1)
        lmax = fmaxf(lmax, __shfl_xor_sync(0xffffffffu, lmax, o));
    if ((tid & 31) == 0) red[tid >> 5] = lmax;
    __syncthreads();
    if (tid < 32) {
        float v = red[tid & 7];
        #pragma unroll
        for (int o = 4; o > 0; o >>= 1)
            v = fmaxf(v, __shfl_xor_sync(0xffffffffu, v, o));
        if (tid == 0) red[0] = v;
    }
    __syncthreads();
    const float rmax = red[0];
    __syncthreads();

    // pass 2: exp + sum (cache exp in smem)
    float lsum = 0.f;
    for (int t = tid; t <= s; t += 256) {
        const float e = __expf(buf[t] - rmax);
        buf[t] = e;
        lsum += e;
    }
    #pragma unroll
    for (int o = 16; o > 0; o >>= 1)
        lsum += __shfl_xor_sync(0xffffffffu, lsum, o);
    if ((tid & 31) == 0) red[tid >> 5] = lsum;
    __syncthreads();
    if (tid < 32) {
        float v = red[tid & 7];
        #pragma unroll
        for (int o = 4; o > 0; o >>= 1)
            v += __shfl_xor_sync(0xffffffffu, v, o);
        if (tid == 0) red[0] = v;
    }
    __syncthreads();
    const float inv = 1.f / red[0];

    // pass 3: write
    for (int t = tid; t < SEQ; t += 256)
        p[t] = (t <= s) ? buf[t] * inv : 0.f;
}

// ---------------------------------------------------------------------------
// Launch
// ---------------------------------------------------------------------------
extern "C" void kernel_launch(void* const* d_in, const int* in_sizes, int n_in,
                              void* d_out, int out_size)
{
    const float* x  = (const float*)d_in[0];
    const float* Wk = (const float*)d_in[1];
    const float* bk = (const float*)d_in[2];
    const float* Wq = (const float*)d_in[3];
    const float* bq = (const float*)d_in[4];
    const float* Wv = (const float*)d_in[5];
    const float* bv = (const float*)d_in[6];
    float* out = (float*)d_out;

    float* K; cudaGetSymbolAddress((void**)&K, g_K);
    float* Q; cudaGetSymbolAddress((void**)&Q, g_Q);
    float* V; cudaGetSymbolAddress((void**)&V, g_V);
    float* S; cudaGetSymbolAddress((void**)&S, g_S);

    // 1) Projections: K/Q/V = x @ W^T + b, fused into one launch (z selects W)
    {
        dim3 grid(EMB / BN, MROWS / BM, 3);
        gemm_nt_tf32<true, false><<<grid, 256>>>(
            x, Wk, Wq, Wv, bk, bq, bv, K, Q, V,
            MROWS, EMB, EMB, 1.f, 0, 0, 0);
    }

    // 2) sim = K @ Q^T / sqrt(E), batched, causal block skip
    {
        dim3 grid(SEQ / BN, SEQ / BM, BATCH);
        const float scale = 1.f / sqrtf((float)EMB);
        gemm_nt_tf32<false, true><<<grid, 256>>>(
            K, Q, nullptr, nullptr, nullptr, nullptr, nullptr, S, nullptr, nullptr,
            SEQ, SEQ, EMB, scale,
            (size_t)SEQ * EMB, (size_t)SEQ * EMB, (size_t)SEQ * SEQ);
    }

    // 3) causal softmax rows
    softmax_causal_kernel<<<BATCH * SEQ, 256>>>(S);

    // 4) out = P @ V, batched, k-limited by causality
    {
        dim3 grid(EMB / BN, SEQ / BM, BATCH);
        gemm_nn_tf32_causal<<<grid, 256>>>(
            S, V, out, SEQ, EMB, SEQ,
            (size_t)SEQ * SEQ, (size_t)SEQ * EMB, (size_t)SEQ * EMB);
    }
}